// round 2
// baseline (speedup 1.0000x reference)
#include <cuda_runtime.h>
#include <cuda_bf16.h>

#define NN 100000
#define NE 1600000
#define DD 128

// ---------------- scratch (device globals; no allocation allowed) ----------
__device__ int   g_off[NN + 1];     // CSR row offsets (by dst)
__device__ int   g_cnt[NN];         // histogram, then scatter cursor
__device__ float g_inv[NN];         // 1 / max(deg, 1)
__device__ int   g_srcs[NE];        // src indices bucketed by dst
__device__ int   g_src32[NE];      // normalized edge list (int32)
__device__ int   g_dst32[NE];
__device__ int   g_odd_nz;         // dtype-detect flag: nonzero -> edges are int32
__device__ __align__(16) float g_mean[NN * DD];   // mean-aggregated features
__device__ __align__(16) float g_h[NN * DD];      // hidden layer activations

// ---------------- edge dtype detection + normalization ----------------------
// If edge_index is int64 (values < 2^31), every odd int32 word is 0.
// If it is int32 (random 0..NN), odd words are ~never all zero.
__global__ void k_detect(const int* __restrict__ ei32) {
    int i = threadIdx.x + blockIdx.x * blockDim.x;   // sample 2048 odd words
    if (i < 2048 && ei32[2 * i + 1] != 0) atomicOr(&g_odd_nz, 1);
}

__global__ void k_cvt(const void* __restrict__ ei) {
    int i = blockIdx.x * blockDim.x + threadIdx.x;
    if (i >= NE) return;
    if (g_odd_nz) {   // int32 layout
        const int* p = (const int*)ei;
        g_src32[i] = p[i];
        g_dst32[i] = p[NE + i];
    } else {          // int64 layout
        const long long* p = (const long long*)ei;
        g_src32[i] = (int)p[i];
        g_dst32[i] = (int)p[NE + i];
    }
}

// ---------------- graph build ----------------------------------------------
__global__ void k_zero_cnt() {
    int i = blockIdx.x * blockDim.x + threadIdx.x;
    if (i < NN) g_cnt[i] = 0;
    if (i == 0) g_odd_nz = 0;
}

__global__ void k_hist() {
    int i = blockIdx.x * blockDim.x + threadIdx.x;
    if (i < NE) {
        int d = g_dst32[i];
        if (d >= 0 && d < NN) atomicAdd(&g_cnt[d], 1);
    }
}

// single-block exclusive scan over 100k counts (chunks of 1024, carried)
__global__ void k_scan() {
    __shared__ int wsum[32];
    __shared__ int s_carry;
    int tid = threadIdx.x;
    int lane = tid & 31, wid = tid >> 5;
    if (tid == 0) s_carry = 0;
    __syncthreads();
    for (int base = 0; base < NN; base += 1024) {
        int i = base + tid;
        int v = (i < NN) ? g_cnt[i] : 0;
        int x = v;
        #pragma unroll
        for (int o = 1; o < 32; o <<= 1) {
            int t = __shfl_up_sync(0xffffffffu, x, o);
            if (lane >= o) x += t;
        }
        if (lane == 31) wsum[wid] = x;
        __syncthreads();
        if (wid == 0) {
            int w = wsum[lane];
            #pragma unroll
            for (int o = 1; o < 32; o <<= 1) {
                int t = __shfl_up_sync(0xffffffffu, w, o);
                if (lane >= o) w += t;
            }
            wsum[lane] = w;
        }
        __syncthreads();
        int excl  = x - v + (wid ? wsum[wid - 1] : 0);
        int carry = s_carry;
        int total = wsum[31];
        if (i < NN) {
            g_off[i] = carry + excl;
            g_inv[i] = 1.0f / (float)(v > 0 ? v : 1);
            g_cnt[i] = 0;                       // reset for scatter cursor
        }
        __syncthreads();
        if (tid == 0) s_carry = carry + total;
        __syncthreads();
    }
    if (threadIdx.x == 0) g_off[NN] = s_carry;
}

__global__ void k_scatter() {
    int i = blockIdx.x * blockDim.x + threadIdx.x;
    if (i < NE) {
        int d = g_dst32[i];
        if (d >= 0 && d < NN) {
            int pos = g_off[d] + atomicAdd(&g_cnt[d], 1);
            g_srcs[pos] = g_src32[i];
        }
    }
}

// ---------------- mean aggregation: one warp per node -----------------------
__global__ __launch_bounds__(256) void k_agg(const float* __restrict__ in) {
    int node = blockIdx.x * 8 + (threadIdx.x >> 5);
    if (node >= NN) return;
    int lane = threadIdx.x & 31;
    int s = g_off[node], e = g_off[node + 1];
    float4 acc = make_float4(0.f, 0.f, 0.f, 0.f);
    int j = s;
    for (; j + 3 < e; j += 4) {
        int s0 = g_srcs[j], s1 = g_srcs[j + 1], s2 = g_srcs[j + 2], s3 = g_srcs[j + 3];
        float4 a = __ldg((const float4*)(in + (size_t)s0 * DD + lane * 4));
        float4 b = __ldg((const float4*)(in + (size_t)s1 * DD + lane * 4));
        float4 c = __ldg((const float4*)(in + (size_t)s2 * DD + lane * 4));
        float4 d = __ldg((const float4*)(in + (size_t)s3 * DD + lane * 4));
        acc.x += a.x + b.x + c.x + d.x;
        acc.y += a.y + b.y + c.y + d.y;
        acc.z += a.z + b.z + c.z + d.z;
        acc.w += a.w + b.w + c.w + d.w;
    }
    for (; j < e; ++j) {
        int s0 = g_srcs[j];
        float4 a = __ldg((const float4*)(in + (size_t)s0 * DD + lane * 4));
        acc.x += a.x; acc.y += a.y; acc.z += a.z; acc.w += a.w;
    }
    float inv = g_inv[node];
    acc.x *= inv; acc.y *= inv; acc.z *= inv; acc.w *= inv;
    *((float4*)(g_mean + (size_t)node * DD + lane * 4)) = acc;
}

// ---------------- fused concat-GEMM: out = [mean||feat] @ [Wl||Wr]^T + b ----
// BM=128, BN=128, BK=8, 256 threads, 8x8 micro-tile
__global__ __launch_bounds__(256) void k_gemm(
    const float* __restrict__ A2,   // feat (self) rows
    const float* __restrict__ Wl, const float* __restrict__ Wr,
    const float* __restrict__ bias, float* __restrict__ out, int relu)
{
    __shared__ float As[8][132];
    __shared__ float Bs[8][132];
    int tid = threadIdx.x;
    int m0 = blockIdx.x * 128;

    int arow = tid >> 1;           // 0..127
    int akq  = (tid & 1) * 4;      // 0 or 4
    int bo   = tid & 127;          // output channel
    int bkh  = (tid >> 7) * 4;     // 0 or 4

    int tx = tid & 15, ty = tid >> 4;   // 16x16 thread grid

    float acc[8][8];
    #pragma unroll
    for (int i = 0; i < 8; ++i)
        #pragma unroll
        for (int j = 0; j < 8; ++j) acc[i][j] = 0.f;

    int grow = m0 + arow;
    bool rok = (grow < NN);

    for (int kt = 0; kt < 32; ++kt) {
        const float* A = (kt < 16) ? g_mean : A2;
        const float* W = (kt < 16) ? Wl : Wr;
        int kb = (kt & 15) * 8;

        float4 av = make_float4(0.f, 0.f, 0.f, 0.f);
        if (rok) av = *(const float4*)(A + (size_t)grow * DD + kb + akq);
        float4 bv = *(const float4*)(W + (size_t)bo * DD + kb + bkh);

        __syncthreads();
        As[akq + 0][arow] = av.x; As[akq + 1][arow] = av.y;
        As[akq + 2][arow] = av.z; As[akq + 3][arow] = av.w;
        Bs[bkh + 0][bo] = bv.x; Bs[bkh + 1][bo] = bv.y;
        Bs[bkh + 2][bo] = bv.z; Bs[bkh + 3][bo] = bv.w;
        __syncthreads();

        #pragma unroll
        for (int k = 0; k < 8; ++k) {
            float4 a0 = *(const float4*)&As[k][ty * 8];
            float4 a1 = *(const float4*)&As[k][ty * 8 + 4];
            float4 b0 = *(const float4*)&Bs[k][tx * 8];
            float4 b1 = *(const float4*)&Bs[k][tx * 8 + 4];
            float ra[8] = {a0.x, a0.y, a0.z, a0.w, a1.x, a1.y, a1.z, a1.w};
            float rb[8] = {b0.x, b0.y, b0.z, b0.w, b1.x, b1.y, b1.z, b1.w};
            #pragma unroll
            for (int i = 0; i < 8; ++i)
                #pragma unroll
                for (int j = 0; j < 8; ++j)
                    acc[i][j] += ra[i] * rb[j];
        }
    }

    #pragma unroll
    for (int i = 0; i < 8; ++i) {
        int row = m0 + ty * 8 + i;
        if (row >= NN) continue;
        #pragma unroll
        for (int j = 0; j < 8; ++j) {
            int col = tx * 8 + j;
            float v = acc[i][j] + __ldg(&bias[col]);
            if (relu) v = fmaxf(v, 0.f);
            out[(size_t)row * DD + col] = v;
        }
    }
}

// ---------------- launch ----------------------------------------------------
extern "C" void kernel_launch(void* const* d_in, const int* in_sizes, int n_in,
                              void* d_out, int out_size) {
    const float* x   = (const float*)d_in[0];
    const void*  ei  = d_in[1];                  // [2, NE], int32 OR int64
    const float* W1l = (const float*)d_in[2];
    const float* b1l = (const float*)d_in[3];
    const float* W1r = (const float*)d_in[4];
    const float* W2l = (const float*)d_in[5];
    const float* b2l = (const float*)d_in[6];
    const float* W2r = (const float*)d_in[7];
    float* out = (float*)d_out;

    // graph build (once per launch, reused by both layers)
    k_zero_cnt<<<(NN + 255) / 256, 256>>>();
    k_detect<<<8, 256>>>((const int*)ei);
    k_cvt<<<(NE + 255) / 256, 256>>>(ei);
    k_hist<<<(NE + 255) / 256, 256>>>();
    k_scan<<<1, 1024>>>();
    k_scatter<<<(NE + 255) / 256, 256>>>();

    int aggGrid  = (NN + 7) / 8;
    int gemmGrid = (NN + 127) / 128;

    // layer 1: mean(x) -> g_mean ; h = relu([mean||x] @ [W1l||W1r]^T + b1)
    k_agg<<<aggGrid, 256>>>(x);
    k_gemm<<<gemmGrid, 256>>>(x, W1l, W1r, b1l, g_h, 1);

    // layer 2: mean(h) -> g_mean ; out = [mean||h] @ [W2l||W2r]^T + b2
    k_agg<<<aggGrid, 256>>>(g_h);
    k_gemm<<<gemmGrid, 256>>>(g_h, W2l, W2r, b2l, out, 0);
}

// round 3
// speedup vs baseline: 1.3127x; 1.3127x over previous
#include <cuda_runtime.h>
#include <cuda_bf16.h>

#define NN 100000
#define NE 1600000
#define DD 128

// ---------------- scratch (device globals; no allocation allowed) ----------
__device__ int   g_off[NN + 1];     // CSR row offsets (by dst)
__device__ int   g_cnt[NN];         // histogram, then scatter cursor
__device__ float g_inv[NN];         // 1 / max(deg, 1)
__device__ int   g_srcs[NE];        // src indices bucketed by dst
__device__ int   g_src32[NE];       // normalized edge list (int32)
__device__ int   g_dst32[NE];
__device__ int   g_odd_nz;          // dtype-detect flag: nonzero -> edges are int32
__device__ __align__(16) float g_mean[NN * DD];   // mean-aggregated features
__device__ __align__(16) float g_h[NN * DD];      // hidden layer activations

// ---------------- edge dtype detection + normalization ----------------------
__global__ void k_detect(const int* __restrict__ ei32) {
    int i = threadIdx.x + blockIdx.x * blockDim.x;   // sample 2048 odd words
    if (i < 2048 && ei32[2 * i + 1] != 0) atomicOr(&g_odd_nz, 1);
}

__global__ void k_cvt(const void* __restrict__ ei) {
    int i = blockIdx.x * blockDim.x + threadIdx.x;
    if (i >= NE) return;
    if (g_odd_nz) {   // int32 layout
        const int* p = (const int*)ei;
        g_src32[i] = p[i];
        g_dst32[i] = p[NE + i];
    } else {          // int64 layout
        const long long* p = (const long long*)ei;
        g_src32[i] = (int)p[i];
        g_dst32[i] = (int)p[NE + i];
    }
}

// ---------------- graph build ----------------------------------------------
__global__ void k_zero_cnt() {
    int i = blockIdx.x * blockDim.x + threadIdx.x;
    if (i < NN) g_cnt[i] = 0;
    if (i == 0) g_odd_nz = 0;
}

__global__ void k_hist() {
    int i = blockIdx.x * blockDim.x + threadIdx.x;
    if (i < NE) {
        int d = g_dst32[i];
        if (d >= 0 && d < NN) atomicAdd(&g_cnt[d], 1);
    }
}

// single-block exclusive scan over 100k counts (chunks of 1024, carried)
__global__ void k_scan() {
    __shared__ int wsum[32];
    __shared__ int s_carry;
    int tid = threadIdx.x;
    int lane = tid & 31, wid = tid >> 5;
    if (tid == 0) s_carry = 0;
    __syncthreads();
    for (int base = 0; base < NN; base += 1024) {
        int i = base + tid;
        int v = (i < NN) ? g_cnt[i] : 0;
        int x = v;
        #pragma unroll
        for (int o = 1; o < 32; o <<= 1) {
            int t = __shfl_up_sync(0xffffffffu, x, o);
            if (lane >= o) x += t;
        }
        if (lane == 31) wsum[wid] = x;
        __syncthreads();
        if (wid == 0) {
            int w = wsum[lane];
            #pragma unroll
            for (int o = 1; o < 32; o <<= 1) {
                int t = __shfl_up_sync(0xffffffffu, w, o);
                if (lane >= o) w += t;
            }
            wsum[lane] = w;
        }
        __syncthreads();
        int excl  = x - v + (wid ? wsum[wid - 1] : 0);
        int carry = s_carry;
        int total = wsum[31];
        if (i < NN) {
            g_off[i] = carry + excl;
            g_inv[i] = 1.0f / (float)(v > 0 ? v : 1);
            g_cnt[i] = 0;                       // reset for scatter cursor
        }
        __syncthreads();
        if (tid == 0) s_carry = carry + total;
        __syncthreads();
    }
    if (threadIdx.x == 0) g_off[NN] = s_carry;
}

__global__ void k_scatter() {
    int i = blockIdx.x * blockDim.x + threadIdx.x;
    if (i < NE) {
        int d = g_dst32[i];
        if (d >= 0 && d < NN) {
            int pos = g_off[d] + atomicAdd(&g_cnt[d], 1);
            g_srcs[pos] = g_src32[i];
        }
    }
}

// ---------------- mean aggregation: one warp per node -----------------------
__global__ __launch_bounds__(256) void k_agg(const float* __restrict__ in) {
    int node = blockIdx.x * 8 + (threadIdx.x >> 5);
    if (node >= NN) return;
    int lane = threadIdx.x & 31;
    int s = g_off[node], e = g_off[node + 1];
    float4 acc = make_float4(0.f, 0.f, 0.f, 0.f);
    int j = s;
    for (; j + 3 < e; j += 4) {
        int s0 = g_srcs[j], s1 = g_srcs[j + 1], s2 = g_srcs[j + 2], s3 = g_srcs[j + 3];
        float4 a = __ldg((const float4*)(in + (size_t)s0 * DD + lane * 4));
        float4 b = __ldg((const float4*)(in + (size_t)s1 * DD + lane * 4));
        float4 c = __ldg((const float4*)(in + (size_t)s2 * DD + lane * 4));
        float4 d = __ldg((const float4*)(in + (size_t)s3 * DD + lane * 4));
        acc.x += a.x + b.x + c.x + d.x;
        acc.y += a.y + b.y + c.y + d.y;
        acc.z += a.z + b.z + c.z + d.z;
        acc.w += a.w + b.w + c.w + d.w;
    }
    for (; j < e; ++j) {
        int s0 = g_srcs[j];
        float4 a = __ldg((const float4*)(in + (size_t)s0 * DD + lane * 4));
        acc.x += a.x; acc.y += a.y; acc.z += a.z; acc.w += a.w;
    }
    float inv = g_inv[node];
    acc.x *= inv; acc.y *= inv; acc.z *= inv; acc.w *= inv;
    *((float4*)(g_mean + (size_t)node * DD + lane * 4)) = acc;
}

// ---------------- fused concat-GEMM: out = [mean||feat] @ [Wl||Wr]^T + b ----
// BM=128, BN=64, BK=16, 256 threads, 8x4 micro-tile (32 accumulators).
// No staging arrays -> no local-memory spill risk.
__global__ __launch_bounds__(256) void k_gemm(
    const float* __restrict__ A2,   // feat (self) rows
    const float* __restrict__ Wl, const float* __restrict__ Wr,
    const float* __restrict__ bias, float* __restrict__ out, int relu)
{
    __shared__ float As[16][132];   // [k][m]
    __shared__ float Bs[16][68];    // [k][n]
    int tid = threadIdx.x;
    int m0 = blockIdx.x * 128;
    int n0 = blockIdx.y * 64;

    // A load mapping: 128 rows x 16 k / 256 thr = 8 floats (2 float4) each
    int arow = tid >> 1;            // 0..127
    int akq  = (tid & 1) * 8;       // 0 or 8
    // B load mapping: 64 rows x 16 k / 256 thr = 4 floats (1 float4) each
    int brow = tid >> 2;            // 0..63 (output channel within tile)
    int bkq  = (tid & 3) * 4;       // 0,4,8,12

    int tx = tid & 15;              // n micro: 4 cols at tx*4
    int ty = tid >> 4;              // m micro: 8 rows at ty*8

    float4 acc0 = make_float4(0.f,0.f,0.f,0.f);
    float4 acc1 = acc0, acc2 = acc0, acc3 = acc0;
    float4 acc4 = acc0, acc5 = acc0, acc6 = acc0, acc7 = acc0;

    int grow = m0 + arow;
    bool rok = (grow < NN);

    for (int kt = 0; kt < 16; ++kt) {          // 8 tiles of mean-half, 8 of self-half
        const float* A = (kt < 8) ? g_mean : A2;
        const float* W = (kt < 8) ? Wl : Wr;
        int kb = (kt & 7) * 16;

        float4 av0 = make_float4(0.f,0.f,0.f,0.f), av1 = av0;
        if (rok) {
            av0 = *(const float4*)(A + (size_t)grow * DD + kb + akq);
            av1 = *(const float4*)(A + (size_t)grow * DD + kb + akq + 4);
        }
        float4 bv = *(const float4*)(W + (size_t)(n0 + brow) * DD + kb + bkq);

        __syncthreads();
        As[akq + 0][arow] = av0.x; As[akq + 1][arow] = av0.y;
        As[akq + 2][arow] = av0.z; As[akq + 3][arow] = av0.w;
        As[akq + 4][arow] = av1.x; As[akq + 5][arow] = av1.y;
        As[akq + 6][arow] = av1.z; As[akq + 7][arow] = av1.w;
        Bs[bkq + 0][brow] = bv.x;  Bs[bkq + 1][brow] = bv.y;
        Bs[bkq + 2][brow] = bv.z;  Bs[bkq + 3][brow] = bv.w;
        __syncthreads();

        #pragma unroll
        for (int k = 0; k < 16; ++k) {
            float4 a0 = *(const float4*)&As[k][ty * 8];
            float4 a1 = *(const float4*)&As[k][ty * 8 + 4];
            float4 b  = *(const float4*)&Bs[k][tx * 4];
            acc0.x += a0.x * b.x; acc0.y += a0.x * b.y; acc0.z += a0.x * b.z; acc0.w += a0.x * b.w;
            acc1.x += a0.y * b.x; acc1.y += a0.y * b.y; acc1.z += a0.y * b.z; acc1.w += a0.y * b.w;
            acc2.x += a0.z * b.x; acc2.y += a0.z * b.y; acc2.z += a0.z * b.z; acc2.w += a0.z * b.w;
            acc3.x += a0.w * b.x; acc3.y += a0.w * b.y; acc3.z += a0.w * b.z; acc3.w += a0.w * b.w;
            acc4.x += a1.x * b.x; acc4.y += a1.x * b.y; acc4.z += a1.x * b.z; acc4.w += a1.x * b.w;
            acc5.x += a1.y * b.x; acc5.y += a1.y * b.y; acc5.z += a1.y * b.z; acc5.w += a1.y * b.w;
            acc6.x += a1.z * b.x; acc6.y += a1.z * b.y; acc6.z += a1.z * b.z; acc6.w += a1.z * b.w;
            acc7.x += a1.w * b.x; acc7.y += a1.w * b.y; acc7.z += a1.w * b.z; acc7.w += a1.w * b.w;
        }
    }

    float4 bv = *(const float4*)(bias + n0 + tx * 4);

    float4 r[8] = {acc0, acc1, acc2, acc3, acc4, acc5, acc6, acc7};
    #pragma unroll
    for (int i = 0; i < 8; ++i) {
        int row = m0 + ty * 8 + i;
        if (row >= NN) continue;
        float4 v = r[i];
        v.x += bv.x; v.y += bv.y; v.z += bv.z; v.w += bv.w;
        if (relu) {
            v.x = fmaxf(v.x, 0.f); v.y = fmaxf(v.y, 0.f);
            v.z = fmaxf(v.z, 0.f); v.w = fmaxf(v.w, 0.f);
        }
        *(float4*)(out + (size_t)row * DD + n0 + tx * 4) = v;
    }
}

// ---------------- launch ----------------------------------------------------
extern "C" void kernel_launch(void* const* d_in, const int* in_sizes, int n_in,
                              void* d_out, int out_size) {
    const float* x   = (const float*)d_in[0];
    const void*  ei  = d_in[1];                  // [2, NE], int32 OR int64
    const float* W1l = (const float*)d_in[2];
    const float* b1l = (const float*)d_in[3];
    const float* W1r = (const float*)d_in[4];
    const float* W2l = (const float*)d_in[5];
    const float* b2l = (const float*)d_in[6];
    const float* W2r = (const float*)d_in[7];
    float* out = (float*)d_out;

    // graph build (once per launch, reused by both layers)
    k_zero_cnt<<<(NN + 255) / 256, 256>>>();
    k_detect<<<8, 256>>>((const int*)ei);
    k_cvt<<<(NE + 255) / 256, 256>>>(ei);
    k_hist<<<(NE + 255) / 256, 256>>>();
    k_scan<<<1, 1024>>>();
    k_scatter<<<(NE + 255) / 256, 256>>>();

    int aggGrid = (NN + 7) / 8;
    dim3 gemmGrid((NN + 127) / 128, 2);

    // layer 1: mean(x) -> g_mean ; h = relu([mean||x] @ [W1l||W1r]^T + b1)
    k_agg<<<aggGrid, 256>>>(x);
    k_gemm<<<gemmGrid, 256>>>(x, W1l, W1r, b1l, g_h, 1);

    // layer 2: mean(h) -> g_mean ; out = [mean||h] @ [W2l||W2r]^T + b2
    k_agg<<<aggGrid, 256>>>(g_h);
    k_gemm<<<gemmGrid, 256>>>(g_h, W2l, W2r, b2l, out, 0);
}